// round 14
// baseline (speedup 1.0000x reference)
#include <cuda_runtime.h>
#include <cuda_fp16.h>
#include <cstdint>

#define NN 50000
#define NNP 50048
#define EE 400000
#define DD 300
#define KP 304
#define KP2 152
#define KU4 38
#define WNP 320
#define LL 5
#define CC 128
#define NGR 256
#define BN_EPS 1e-5f

#define BM 128
#define BN 160
#define NCH 19
#define MT ((NNP) / BM)
#define LDA 24
#define LDB 168
#define STG 3
#define SMEMSZ (STG * (BM * LDA + 16 * LDB) * 2)   // 34560

// ---------------- static device scratch ----------------
__device__ int   g_is64;
__device__ int   g_cnt[NN];
__device__ int   g_off[NN + 1];
__device__ int   g_pos[NN];
__device__ int   g_srcl[EE];
__device__ int   g_goff[NGR + 1];
__device__ int   g_bsum[128];
__device__ int   g_bpre[128];
__device__ __align__(16) __half g_z0h[(size_t)NN * DD];   // GEMM2 out
__device__ __align__(16) __half g_z1h[(size_t)NN * DD];   // GEMM1 out
__device__ __align__(16) __half g_hbuf[(size_t)NN * KP];  // bnrelu'd h / fp16(x), padded
__device__ __align__(16) __half g_a[(size_t)NNP * KP];    // GEMM A operand
__device__ __align__(16) __half g_w[(size_t)2 * LL * KP * WNP];
__device__ float g_colsum[2 * LL * DD];                   // per-GEMM stat slices
__device__ float g_colsq[2 * LL * DD];
__device__ __align__(16) float g_pooled[(size_t)(LL + 1) * NGR * DD];

// ---------------- PTX helpers ----------------
__device__ __forceinline__ uint32_t smem_u32(const void* p) {
    uint32_t a;
    asm("{ .reg .u64 t; cvta.to.shared.u64 t, %1; cvt.u32.u64 %0, t; }" : "=r"(a) : "l"(p));
    return a;
}
__device__ __forceinline__ void cp16(uint32_t d, const void* s) {
    asm volatile("cp.async.cg.shared.global [%0], [%1], 16;" :: "r"(d), "l"(s) : "memory");
}
__device__ __forceinline__ void cp_commit() {
    asm volatile("cp.async.commit_group;" ::: "memory");
}
__device__ __forceinline__ void cp_wait0() {
    asm volatile("cp.async.wait_group 0;" ::: "memory");
}
__device__ __forceinline__ void cp_wait1() {
    asm volatile("cp.async.wait_group 1;" ::: "memory");
}
__device__ __forceinline__ void ldsm_x4(uint32_t* r, uint32_t addr) {
    asm volatile("ldmatrix.sync.aligned.m8n8.x4.shared.b16 {%0,%1,%2,%3}, [%4];"
                 : "=r"(r[0]), "=r"(r[1]), "=r"(r[2]), "=r"(r[3]) : "r"(addr));
}
__device__ __forceinline__ void ldsm_x2t(uint32_t* r, uint32_t addr) {
    asm volatile("ldmatrix.sync.aligned.m8n8.x2.trans.shared.b16 {%0,%1}, [%2];"
                 : "=r"(r[0]), "=r"(r[1]) : "r"(addr));
}
__device__ __forceinline__ void mma16816(float* d, const uint32_t* a, const uint32_t* b) {
    asm volatile("mma.sync.aligned.m16n8k16.row.col.f32.f16.f16.f32 "
                 "{%0,%1,%2,%3}, {%4,%5,%6,%7}, {%8,%9}, {%0,%1,%2,%3};"
                 : "+f"(d[0]), "+f"(d[1]), "+f"(d[2]), "+f"(d[3])
                 : "r"(a[0]), "r"(a[1]), "r"(a[2]), "r"(a[3]), "r"(b[0]), "r"(b[1]));
}
__device__ __forceinline__ int idx_at(const void* p, long long i) {
    if (g_is64) return (int)((const long long*)p)[i];
    return ((const int*)p)[i];
}
// inline BN coeff computation from a stat slice
__device__ __forceinline__ void bn_coeff(int lw, int c, const float* gam,
                                         const float* bet, float& sc, float& sh) {
    float m = g_colsum[lw * DD + c] * (1.f / NN);
    float v = g_colsq[lw * DD + c] * (1.f / NN) - m * m;
    float r = rsqrtf(v + BN_EPS);
    sc = r * gam[c];
    sh = bet[c] - m * sc;
}

// ---------------- setup kernels ----------------
__global__ void k_detect(const void* ei) {
    const int* w = (const int*)ei;
    int all0 = 1;
    for (int i = 0; i < 128; i++)
        if (w[2 * i + 1] != 0) { all0 = 0; break; }
    g_is64 = all0;
}

__global__ void k_wprep(const float* __restrict__ W1, const float* __restrict__ b1,
                        const float* __restrict__ W2, const float* __restrict__ b2) {
    int lw = blockIdx.x / KP;
    int k  = blockIdx.x % KP;
    int n  = threadIdx.x;
    int layer = lw >> 1;
    const float* W = (lw & 1) ? W2 : W1;
    const float* b = (lw & 1) ? b2 : b1;
    float v = 0.f;
    if (n < DD) {
        if (k < DD)       v = W[(size_t)layer * DD * DD + (size_t)k * DD + n];
        else if (k == DD) v = b[layer * DD + n];
    }
    g_w[(size_t)lw * KP * WNP + (size_t)k * WNP + n] = __float2half_rn(v);
}

// zero g_a tail rows + hbuf pad cols (300..303) for all rows
__global__ void k_padinit() {
    int idx = blockIdx.x * 256 + threadIdx.x;
    if (idx < NN) {
        uint2* p = (uint2*)(g_hbuf + (size_t)idx * KP + 300);
        *p = make_uint2(0, 0);
    }
    if (idx < (NNP - NN) * KU4) {
        int row = NN + idx / KU4, s = idx % KU4;
        ((uint4*)g_a)[(size_t)row * KU4 + s] = make_uint4(0, 0, 0, 0);
    }
}

__global__ void k_zero() {
    int i = blockIdx.x * blockDim.x + threadIdx.x;
    if (i < NN) g_cnt[i] = 0;
    if (i < 2 * LL * DD) { g_colsum[i] = 0.f; g_colsq[i] = 0.f; }
}

__global__ void k_count(const void* __restrict__ ei) {
    int e = blockIdx.x * blockDim.x + threadIdx.x;
    if (e < EE) {
        int d = idx_at(ei, (long long)EE + e);
        d = max(0, min(NN - 1, d));
        atomicAdd(&g_cnt[d], 1);
    }
}

__global__ void k_scan1() {
    __shared__ int s[512];
    int b = blockIdx.x, t = threadIdx.x, i = b * 512 + t;
    int v = (i < NN) ? g_cnt[i] : 0;
    s[t] = v;
    __syncthreads();
    for (int d = 1; d < 512; d <<= 1) {
        int y = (t >= d) ? s[t - d] : 0;
        __syncthreads();
        s[t] += y;
        __syncthreads();
    }
    if (i < NN) g_cnt[i] = s[t] - v;
    if (t == 511) g_bsum[b] = s[511];
}
__global__ void k_scan2(int nb) {
    __shared__ int s[128];
    int t = threadIdx.x;
    int v = (t < nb) ? g_bsum[t] : 0;
    s[t] = v;
    __syncthreads();
    for (int d = 1; d < 128; d <<= 1) {
        int y = (t >= d) ? s[t - d] : 0;
        __syncthreads();
        s[t] += y;
        __syncthreads();
    }
    if (t < nb) g_bpre[t] = s[t] - v;
    if (t == nb - 1) g_off[NN] = s[t];
}
__global__ void k_scan3() {
    int i = blockIdx.x * blockDim.x + threadIdx.x;
    if (i < NN) {
        int e = g_bpre[i >> 9] + g_cnt[i];
        g_off[i] = e;
        g_pos[i] = e;
    }
}

__global__ void k_fill(const void* __restrict__ ei) {
    int e = blockIdx.x * blockDim.x + threadIdx.x;
    if (e < EE) {
        int d = idx_at(ei, (long long)EE + e);
        d = max(0, min(NN - 1, d));
        int srcv = idx_at(ei, e);
        srcv = max(0, min(NN - 1, srcv));
        int p = atomicAdd(&g_pos[d], 1);
        if (p >= 0 && p < EE) g_srcl[p] = srcv;
    }
}

__global__ void k_goff(const void* __restrict__ batch) {
    int g = blockIdx.x * blockDim.x + threadIdx.x;
    if (g > NGR) return;
    int lo = 0, hi = NN;
    while (lo < hi) {
        int mid = (lo + hi) >> 1;
        if (idx_at(batch, mid) < g) lo = mid + 1; else hi = mid;
    }
    g_goff[g] = lo;
}

// ---------------- fused fp16(x) -> hbuf + pool depth 0 ----------------
// grid (NGR, 2), block 80: thread = col pair gy*75+t
__global__ void k_xpool(const float* __restrict__ x) {
    int g = blockIdx.x;
    int t = threadIdx.x;
    if (t >= 75) return;
    int c2 = blockIdx.y * 75 + t;
    int s0 = g_goff[g], s1 = g_goff[g + 1];
    s0 = max(0, min(NN, s0));
    s1 = max(s0, min(NN, s1));
    float ax = 0.f, ay = 0.f;
    for (int i = s0; i < s1; i++) {
        float2 f = *(const float2*)(x + (size_t)i * DD + 2 * c2);
        *(__half2*)(g_hbuf + (size_t)i * KP + 2 * c2) = __floats2half2_rn(f.x, f.y);
        ax += f.x; ay += f.y;
    }
    float inv = 1.f / fmaxf((float)(s1 - s0), 1.f);
    float* pr = g_pooled + (size_t)g * DD + 2 * c2;
    pr[0] = ax * inv;
    pr[1] = ay * inv;
}

// ---------------- aggregation: warp/node, uint4 + HADD2 ----------------
__global__ void __launch_bounds__(256) k_agg() {
    int w = blockIdx.x * 8 + (threadIdx.x >> 5);
    int lane = threadIdx.x & 31;
    if (w >= NN) return;
    const uint4* hb = (const uint4*)g_hbuf;
    const uint4* rowp = hb + (size_t)w * KU4;
    bool hasB = lane < (KU4 - 32);   // lanes 0..5

    uint4 va = rowp[lane];
    uint4 vb = hasB ? rowp[32 + lane] : make_uint4(0, 0, 0, 0);
    __half2 aA[4], aB[4];
    *(uint4*)aA = va;
    *(uint4*)aB = vb;

    int s0 = g_off[w], s1 = g_off[w + 1];
    s0 = max(0, min(EE, s0));
    s1 = max(s0, min(EE, s1));

    for (int j = s0; j < s1; j++) {
        int src = g_srcl[j];
        const uint4* r2 = hb + (size_t)src * KU4;
        uint4 u = r2[lane];
        __half2* up = (__half2*)&u;
        aA[0] = __hadd2(aA[0], up[0]);
        aA[1] = __hadd2(aA[1], up[1]);
        aA[2] = __hadd2(aA[2], up[2]);
        aA[3] = __hadd2(aA[3], up[3]);
        if (hasB) {
            uint4 u2 = r2[32 + lane];
            __half2* vp = (__half2*)&u2;
            aB[0] = __hadd2(aB[0], vp[0]);
            aB[1] = __hadd2(aB[1], vp[1]);
            aB[2] = __hadd2(aB[2], vp[2]);
            aB[3] = __hadd2(aB[3], vp[3]);
        }
    }

    // bias cols 300..303 = {1,0,0,0} (lane 5 slot B = cols 296..303)
    if (lane == 5) {
        aB[2] = __floats2half2_rn(1.f, 0.f);
        aB[3] = __floats2half2_rn(0.f, 0.f);
    }

    uint4* ar = (uint4*)g_a + (size_t)w * KU4;
    ar[lane] = *(uint4*)aA;
    if (hasB) ar[32 + lane] = *(uint4*)aB;
}

// ---------------- fp16 GEMM: C(half) = A @ W, stats into slice widx ----------------
__global__ void __launch_bounds__(256, 2) k_gemm(int widx) {
    extern __shared__ __align__(16) char smem[];
    __half* AS = (__half*)smem;                   // [STG][BM][LDA]
    __half* BS = AS + STG * BM * LDA;             // [STG][16][LDB]

    __half* __restrict__ C = (widx & 1) ? g_z0h : g_z1h;
    const __half* __restrict__ W = g_w + (size_t)widx * KP * WNP;
    float* csum = g_colsum + widx * DD;
    float* csq  = g_colsq + widx * DD;

    int tid = threadIdx.x, lane = tid & 31, wid = tid >> 5;
    int warp_m = wid & 1, warp_n = wid >> 1;
    int m0 = blockIdx.y * BM, n0 = blockIdx.x * BN;

    int arow = tid >> 1, aseg = tid & 1;
    const __half* asrc = g_a + (size_t)(m0 + arow) * KP + aseg * 8;

    #define ISSUE(CH, ST)                                                         \
    {                                                                             \
        int k0i = (CH) * 16;                                                      \
        cp16(smem_u32(AS + ((ST) * BM + arow) * LDA + aseg * 8), asrc + k0i);     \
        for (int u = tid; u < 320; u += 256) {                                    \
            int br = u / 20, bc = u % 20;                                         \
            size_t go = (size_t)(k0i + br) * WNP + n0 + bc * 8;                   \
            cp16(smem_u32(BS + ((ST) * 16 + br) * LDB + bc * 8), W + go);         \
        }                                                                         \
        cp_commit();                                                              \
    }

    ISSUE(0, 0);
    ISSUE(1, 1);

    float acc[4][5][4];
    #pragma unroll
    for (int mi = 0; mi < 4; mi++)
        #pragma unroll
        for (int ni = 0; ni < 5; ni++)
            #pragma unroll
            for (int q = 0; q < 4; q++) acc[mi][ni][q] = 0.f;

    int lr = lane & 15, lkh = (lane >> 4) * 8;

    for (int ch = 0; ch < NCH; ch++) {
        if (ch + 2 < NCH) cp_wait1(); else cp_wait0();
        __syncthreads();
        int st = ch % 3;
        if (ch + 2 < NCH) ISSUE(ch + 2, (ch + 2) % 3);

        uint32_t bh[5][2];
        #pragma unroll
        for (int ni = 0; ni < 5; ni++)
            ldsm_x2t(bh[ni], smem_u32(BS + (st * 16 + lr) * LDB + warp_n * 40 + ni * 8));

        #pragma unroll
        for (int mi = 0; mi < 4; mi++) {
            uint32_t ah[4];
            ldsm_x4(ah, smem_u32(AS + (st * BM + warp_m * 64 + mi * 16 + lr) * LDA + lkh));
            #pragma unroll
            for (int ni = 0; ni < 5; ni++)
                mma16816(acc[mi][ni], ah, bh[ni]);
        }
    }
    #undef ISSUE

    // epilogue: fp16 store + fp32 column stats (bias folded via K-row)
    float se[5], so[5], qe[5], qo[5];
    #pragma unroll
    for (int ni = 0; ni < 5; ni++) { se[ni] = so[ni] = qe[ni] = qo[ni] = 0.f; }

    #pragma unroll
    for (int mi = 0; mi < 4; mi++) {
        int r0 = m0 + warp_m * 64 + mi * 16 + (lane >> 2);
        int r1 = r0 + 8;
        bool v0 = r0 < NN, v1 = r1 < NN;
        #pragma unroll
        for (int ni = 0; ni < 5; ni++) {
            int gn = n0 + warp_n * 40 + ni * 8 + (lane & 3) * 2;
            bool vc = gn < DD;
            float o0 = acc[mi][ni][0], o1 = acc[mi][ni][1];
            float o2 = acc[mi][ni][2], o3 = acc[mi][ni][3];
            if (v0 && vc) *(__half2*)(C + (size_t)r0 * DD + gn) = __floats2half2_rn(o0, o1);
            if (v1 && vc) *(__half2*)(C + (size_t)r1 * DD + gn) = __floats2half2_rn(o2, o3);
            if (v0) { se[ni] += o0; so[ni] += o1; qe[ni] += o0 * o0; qo[ni] += o1 * o1; }
            if (v1) { se[ni] += o2; so[ni] += o3; qe[ni] += o2 * o2; qo[ni] += o3 * o3; }
        }
    }
    #pragma unroll
    for (int ni = 0; ni < 5; ni++) {
        #pragma unroll
        for (int d = 4; d < 32; d <<= 1) {
            se[ni] += __shfl_xor_sync(0xffffffffu, se[ni], d);
            so[ni] += __shfl_xor_sync(0xffffffffu, so[ni], d);
            qe[ni] += __shfl_xor_sync(0xffffffffu, qe[ni], d);
            qo[ni] += __shfl_xor_sync(0xffffffffu, qo[ni], d);
        }
    }
    if (lane < 4) {
        #pragma unroll
        for (int ni = 0; ni < 5; ni++) {
            int gn = n0 + warp_n * 40 + ni * 8 + lane * 2;
            if (gn < DD) {
                atomicAdd(&csum[gn], se[ni]);
                atomicAdd(&csum[gn + 1], so[ni]);
                atomicAdd(&csq[gn], qe[ni]);
                atomicAdd(&csq[gn + 1], qo[ni]);
            }
        }
    }
}

// ---------------- bnsplit: relu(BN(z1h)) -> g_a, inline BN coeffs ----------------
// grid (NN+63)/64, block 160: thread = col pair (150 active), 64 rows per block
__global__ void k_bnsplit(const float* __restrict__ gam, const float* __restrict__ bet,
                          int lw) {
    int t = threadIdx.x;
    if (t >= 150) return;
    int r0 = blockIdx.x * 64;
    float scx, shx, scy, shy;
    bn_coeff(lw, 2 * t, gam, bet, scx, shx);
    bn_coeff(lw, 2 * t + 1, gam, bet, scy, shy);
    __half2 sc = __floats2half2_rn(scx, scy);
    __half2 sh = __floats2half2_rn(shx, shy);
    __half2 zero = __floats2half2_rn(0.f, 0.f);
    int rend = min(r0 + 64, NN);
    for (int row = r0; row < rend; row++) {
        __half2 z = *(const __half2*)(g_z1h + (size_t)row * DD + 2 * t);
        *(__half2*)(g_a + (size_t)row * KP + 2 * t) = __hmax2(__hfma2(z, sc, sh), zero);
    }
}

// ---------------- bnpool: relu(BN(z0h)) -> hbuf + pool, inline BN coeffs ----------------
// grid (NGR, 2), block 80: thread = col pair gy*75+t
__global__ void k_bnpool(const float* __restrict__ gam, const float* __restrict__ bet,
                         int lw, int depth) {
    int g = blockIdx.x;
    int t = threadIdx.x;
    if (t >= 75) return;
    int c2 = blockIdx.y * 75 + t;
    float scx, shx, scy, shy;
    bn_coeff(lw, 2 * c2, gam, bet, scx, shx);
    bn_coeff(lw, 2 * c2 + 1, gam, bet, scy, shy);
    __half2 sc = __floats2half2_rn(scx, scy);
    __half2 sh = __floats2half2_rn(shx, shy);
    __half2 zero = __floats2half2_rn(0.f, 0.f);
    int s0 = g_goff[g], s1 = g_goff[g + 1];
    s0 = max(0, min(NN, s0));
    s1 = max(s0, min(NN, s1));
    float ax = 0.f, ay = 0.f;
    for (int i = s0; i < s1; i++) {
        __half2 z = *(const __half2*)(g_z0h + (size_t)i * DD + 2 * c2);
        __half2 h = __hmax2(__hfma2(z, sc, sh), zero);
        *(__half2*)(g_hbuf + (size_t)i * KP + 2 * c2) = h;
        float2 f = __half22float2(h);
        ax += f.x; ay += f.y;
    }
    float inv = 1.f / fmaxf((float)(s1 - s0), 1.f);
    float* pr = g_pooled + ((size_t)depth * NGR + g) * DD + 2 * c2;
    pr[0] = ax * inv;
    pr[1] = ay * inv;
}

__global__ void k_readout(const float* __restrict__ fcW, const float* __restrict__ fcb,
                          float* __restrict__ out) {
    __shared__ float sp[DD];
    int g = blockIdx.x, c = threadIdx.x;
    float acc = 0.f;
    for (int d = 0; d <= LL; d++) {
        const float* pr = g_pooled + ((size_t)d * NGR + g) * DD;
        for (int f = c; f < DD; f += 128) sp[f] = pr[f];
        __syncthreads();
        const float* W = fcW + (size_t)d * DD * CC;
        float a = 0.f;
        #pragma unroll 4
        for (int k = 0; k < DD; k++) a += sp[k] * W[k * CC + c];
        acc += a + fcb[d * CC + c];
        __syncthreads();
    }
    out[g * CC + c] = acc;
}

// ---------------- launch ----------------
extern "C" void kernel_launch(void* const* d_in, const int* in_sizes, int n_in,
                              void* d_out, int out_size) {
    const float* x     = (const float*)d_in[0];
    const void*  ei    = d_in[1];
    const void*  batch = d_in[2];
    const float* W1  = (const float*)d_in[3];
    const float* b1  = (const float*)d_in[4];
    const float* g1  = (const float*)d_in[5];
    const float* be1 = (const float*)d_in[6];
    const float* W2  = (const float*)d_in[7];
    const float* b2  = (const float*)d_in[8];
    const float* bng = (const float*)d_in[9];
    const float* bnb = (const float*)d_in[10];
    const float* fcW = (const float*)d_in[11];
    const float* fcb = (const float*)d_in[12];
    float* out = (float*)d_out;

    cudaFuncSetAttribute(k_gemm, cudaFuncAttributeMaxDynamicSharedMemorySize, SMEMSZ);

    k_detect<<<1, 1>>>(ei);
    k_wprep<<<2 * LL * KP, WNP>>>(W1, b1, W2, b2);
    k_padinit<<<(NN + 255) / 256, 256>>>();
    k_zero<<<(NN + 255) / 256, 256>>>();
    k_count<<<(EE + 255) / 256, 256>>>(ei);
    int nb = (NN + 511) / 512;
    k_scan1<<<nb, 512>>>();
    k_scan2<<<1, 128>>>(nb);
    k_scan3<<<(NN + 255) / 256, 256>>>();
    k_fill<<<(EE + 255) / 256, 256>>>(ei);
    k_goff<<<1, 288>>>(batch);

    dim3 pg(NGR, 2);
    k_xpool<<<pg, 80>>>(x);

    dim3 gg(2, MT);
    for (int i = 0; i < LL; i++) {
        k_agg<<<(NN + 7) / 8, 256>>>();
        k_gemm<<<gg, 256, SMEMSZ>>>(2 * i);
        k_bnsplit<<<(NN + 63) / 64, 160>>>(g1 + i * DD, be1 + i * DD, 2 * i);
        k_gemm<<<gg, 256, SMEMSZ>>>(2 * i + 1);
        k_bnpool<<<pg, 80>>>(bng + i * DD, bnb + i * DD, 2 * i + 1, i + 1);
    }

    k_readout<<<NGR, 128>>>(fcW, fcb, out);
}

// round 15
// speedup vs baseline: 1.2205x; 1.2205x over previous
#include <cuda_runtime.h>
#include <cuda_fp16.h>
#include <cstdint>

#define NN 50000
#define NNP 50048
#define EE 400000
#define DD 300
#define KP 304
#define KP2 152
#define KU4 38
#define WNP 320
#define LL 5
#define CC 128
#define NGR 256
#define BN_EPS 1e-5f

#define BM 128
#define BN 160
#define NCH 19
#define MT ((NNP) / BM)
#define LDA 24
#define LDB 168
#define STG 3
#define SMEMSZ (STG * (BM * LDA + 16 * LDB) * 2)   // 34560

// ---------------- static device scratch ----------------
__device__ int   g_is64;
__device__ int   g_cnt[NN];
__device__ int   g_off[NN + 1];
__device__ int   g_pos[NN];
__device__ int   g_srcl[EE];
__device__ int   g_goff[NGR + 1];
__device__ int   g_bsum[128];
__device__ int   g_bpre[128];
__device__ __align__(16) __half g_z0h[(size_t)NN * DD];   // GEMM2 out
__device__ __align__(16) __half g_z1h[(size_t)NN * DD];   // GEMM1 out
__device__ __align__(16) __half g_hbuf[(size_t)NN * KP];  // bnrelu'd h / fp16(x), padded
__device__ __align__(16) __half g_a[(size_t)NNP * KP];    // GEMM A operand
__device__ __align__(16) __half g_w[(size_t)2 * LL * KP * WNP];
__device__ float g_colsum[DD];
__device__ float g_colsq[DD];
__device__ __align__(16) __half g_sc1h[DD], g_sh1h[DD], g_sc2h[DD], g_sh2h[DD];
__device__ __align__(16) float g_pooled[(size_t)(LL + 1) * NGR * DD];

// ---------------- PTX helpers ----------------
__device__ __forceinline__ uint32_t smem_u32(const void* p) {
    uint32_t a;
    asm("{ .reg .u64 t; cvta.to.shared.u64 t, %1; cvt.u32.u64 %0, t; }" : "=r"(a) : "l"(p));
    return a;
}
__device__ __forceinline__ void cp16(uint32_t d, const void* s) {
    asm volatile("cp.async.cg.shared.global [%0], [%1], 16;" :: "r"(d), "l"(s) : "memory");
}
__device__ __forceinline__ void cp_commit() {
    asm volatile("cp.async.commit_group;" ::: "memory");
}
__device__ __forceinline__ void cp_wait0() {
    asm volatile("cp.async.wait_group 0;" ::: "memory");
}
__device__ __forceinline__ void cp_wait1() {
    asm volatile("cp.async.wait_group 1;" ::: "memory");
}
__device__ __forceinline__ void ldsm_x4(uint32_t* r, uint32_t addr) {
    asm volatile("ldmatrix.sync.aligned.m8n8.x4.shared.b16 {%0,%1,%2,%3}, [%4];"
                 : "=r"(r[0]), "=r"(r[1]), "=r"(r[2]), "=r"(r[3]) : "r"(addr));
}
__device__ __forceinline__ void ldsm_x2t(uint32_t* r, uint32_t addr) {
    asm volatile("ldmatrix.sync.aligned.m8n8.x2.trans.shared.b16 {%0,%1}, [%2];"
                 : "=r"(r[0]), "=r"(r[1]) : "r"(addr));
}
__device__ __forceinline__ void mma16816(float* d, const uint32_t* a, const uint32_t* b) {
    asm volatile("mma.sync.aligned.m16n8k16.row.col.f32.f16.f16.f32 "
                 "{%0,%1,%2,%3}, {%4,%5,%6,%7}, {%8,%9}, {%0,%1,%2,%3};"
                 : "+f"(d[0]), "+f"(d[1]), "+f"(d[2]), "+f"(d[3])
                 : "r"(a[0]), "r"(a[1]), "r"(a[2]), "r"(a[3]), "r"(b[0]), "r"(b[1]));
}
__device__ __forceinline__ int idx_at(const void* p, long long i) {
    if (g_is64) return (int)((const long long*)p)[i];
    return ((const int*)p)[i];
}

// ---------------- setup kernels ----------------
__global__ void k_detect(const void* ei) {
    const int* w = (const int*)ei;
    int all0 = 1;
    for (int i = 0; i < 128; i++)
        if (w[2 * i + 1] != 0) { all0 = 0; break; }
    g_is64 = all0;
}

__global__ void k_wprep(const float* __restrict__ W1, const float* __restrict__ b1,
                        const float* __restrict__ W2, const float* __restrict__ b2) {
    int lw = blockIdx.x / KP;
    int k  = blockIdx.x % KP;
    int n  = threadIdx.x;
    int layer = lw >> 1;
    const float* W = (lw & 1) ? W2 : W1;
    const float* b = (lw & 1) ? b2 : b1;
    float v = 0.f;
    if (n < DD) {
        if (k < DD)       v = W[(size_t)layer * DD * DD + (size_t)k * DD + n];
        else if (k == DD) v = b[layer * DD + n];
    }
    g_w[(size_t)lw * KP * WNP + (size_t)k * WNP + n] = __float2half_rn(v);
}

// fp16(x) -> g_hbuf (KP stride, pad cols zeroed)
__global__ void k_xhalf(const float* __restrict__ x) {
    long long idx = (long long)blockIdx.x * 256 + threadIdx.x;
    if (idx >= (long long)NN * KP2) return;
    int row = (int)(idx / KP2), c2 = (int)(idx - (long long)row * KP2);
    __half2 v = __floats2half2_rn(0.f, 0.f);
    if (c2 < 150) {
        float2 f = *(const float2*)(x + (size_t)row * DD + 2 * c2);
        v = __floats2half2_rn(f.x, f.y);
    }
    *(__half2*)(g_hbuf + (size_t)row * KP + 2 * c2) = v;
}

// zero tail rows of g_a (rows NN..NNP)
__global__ void k_padtail() {
    int idx = blockIdx.x * 256 + threadIdx.x;
    if (idx >= (NNP - NN) * KU4) return;
    int row = NN + idx / KU4, s = idx % KU4;
    ((uint4*)g_a)[(size_t)row * KU4 + s] = make_uint4(0, 0, 0, 0);
}

__global__ void k_zero() {
    int i = blockIdx.x * blockDim.x + threadIdx.x;
    if (i < NN) g_cnt[i] = 0;
    if (i < DD) { g_colsum[i] = 0.f; g_colsq[i] = 0.f; }
}

__global__ void k_count(const void* __restrict__ ei) {
    int e = blockIdx.x * blockDim.x + threadIdx.x;
    if (e < EE) {
        int d = idx_at(ei, (long long)EE + e);
        d = max(0, min(NN - 1, d));
        atomicAdd(&g_cnt[d], 1);
    }
}

__global__ void k_scan1() {
    __shared__ int s[512];
    int b = blockIdx.x, t = threadIdx.x, i = b * 512 + t;
    int v = (i < NN) ? g_cnt[i] : 0;
    s[t] = v;
    __syncthreads();
    for (int d = 1; d < 512; d <<= 1) {
        int y = (t >= d) ? s[t - d] : 0;
        __syncthreads();
        s[t] += y;
        __syncthreads();
    }
    if (i < NN) g_cnt[i] = s[t] - v;
    if (t == 511) g_bsum[b] = s[511];
}
__global__ void k_scan2(int nb) {
    __shared__ int s[128];
    int t = threadIdx.x;
    int v = (t < nb) ? g_bsum[t] : 0;
    s[t] = v;
    __syncthreads();
    for (int d = 1; d < 128; d <<= 1) {
        int y = (t >= d) ? s[t - d] : 0;
        __syncthreads();
        s[t] += y;
        __syncthreads();
    }
    if (t < nb) g_bpre[t] = s[t] - v;
    if (t == nb - 1) g_off[NN] = s[t];
}
__global__ void k_scan3() {
    int i = blockIdx.x * blockDim.x + threadIdx.x;
    if (i < NN) {
        int e = g_bpre[i >> 9] + g_cnt[i];
        g_off[i] = e;
        g_pos[i] = e;
    }
}

__global__ void k_fill(const void* __restrict__ ei) {
    int e = blockIdx.x * blockDim.x + threadIdx.x;
    if (e < EE) {
        int d = idx_at(ei, (long long)EE + e);
        d = max(0, min(NN - 1, d));
        int srcv = idx_at(ei, e);
        srcv = max(0, min(NN - 1, srcv));
        int p = atomicAdd(&g_pos[d], 1);
        if (p >= 0 && p < EE) g_srcl[p] = srcv;
    }
}

__global__ void k_goff(const void* __restrict__ batch) {
    int g = blockIdx.x * blockDim.x + threadIdx.x;
    if (g > NGR) return;
    int lo = 0, hi = NN;
    while (lo < hi) {
        int mid = (lo + hi) >> 1;
        if (idx_at(batch, mid) < g) lo = mid + 1; else hi = mid;
    }
    g_goff[g] = lo;
}

// ---------------- aggregation: warp/node, uint4 + HADD2 ----------------
__global__ void __launch_bounds__(256) k_agg() {
    int w = blockIdx.x * 8 + (threadIdx.x >> 5);
    int lane = threadIdx.x & 31;
    if (w >= NN) return;
    const uint4* hb = (const uint4*)g_hbuf;
    const uint4* rowp = hb + (size_t)w * KU4;
    bool hasB = lane < (KU4 - 32);   // lanes 0..5

    uint4 va = rowp[lane];
    uint4 vb = hasB ? rowp[32 + lane] : make_uint4(0, 0, 0, 0);
    __half2 aA[4], aB[4];
    *(uint4*)aA = va;
    *(uint4*)aB = vb;

    int s0 = g_off[w], s1 = g_off[w + 1];
    s0 = max(0, min(EE, s0));
    s1 = max(s0, min(EE, s1));

    for (int j = s0; j < s1; j++) {
        int src = g_srcl[j];
        const uint4* r2 = hb + (size_t)src * KU4;
        uint4 u = r2[lane];
        __half2* up = (__half2*)&u;
        aA[0] = __hadd2(aA[0], up[0]);
        aA[1] = __hadd2(aA[1], up[1]);
        aA[2] = __hadd2(aA[2], up[2]);
        aA[3] = __hadd2(aA[3], up[3]);
        if (hasB) {
            uint4 u2 = r2[32 + lane];
            __half2* vp = (__half2*)&u2;
            aB[0] = __hadd2(aB[0], vp[0]);
            aB[1] = __hadd2(aB[1], vp[1]);
            aB[2] = __hadd2(aB[2], vp[2]);
            aB[3] = __hadd2(aB[3], vp[3]);
        }
    }

    // bias cols 300..303 = {1,0,0,0} (lane 5 slot B = cols 296..303)
    if (lane == 5) {
        aB[2] = __floats2half2_rn(1.f, 0.f);
        aB[3] = __floats2half2_rn(0.f, 0.f);
    }

    uint4* ar = (uint4*)g_a + (size_t)w * KU4;
    ar[lane] = *(uint4*)aA;
    if (hasB) ar[32 + lane] = *(uint4*)aB;
}

// ---------------- fp16 GEMM: C(half) = A @ W, fp32 stats ----------------
__global__ void __launch_bounds__(256, 2) k_gemm(int widx, int phase) {
    extern __shared__ __align__(16) char smem[];
    __half* AS = (__half*)smem;                   // [STG][BM][LDA]
    __half* BS = AS + STG * BM * LDA;             // [STG][16][LDB]

    __half* __restrict__ C = phase ? g_z0h : g_z1h;
    const __half* __restrict__ W = g_w + (size_t)widx * KP * WNP;

    int tid = threadIdx.x, lane = tid & 31, wid = tid >> 5;
    int warp_m = wid & 1, warp_n = wid >> 1;
    int m0 = blockIdx.y * BM, n0 = blockIdx.x * BN;

    int arow = tid >> 1, aseg = tid & 1;
    const __half* asrc = g_a + (size_t)(m0 + arow) * KP + aseg * 8;

    #define ISSUE(CH, ST)                                                         \
    {                                                                             \
        int k0i = (CH) * 16;                                                      \
        cp16(smem_u32(AS + ((ST) * BM + arow) * LDA + aseg * 8), asrc + k0i);     \
        for (int u = tid; u < 320; u += 256) {                                    \
            int br = u / 20, bc = u % 20;                                         \
            size_t go = (size_t)(k0i + br) * WNP + n0 + bc * 8;                   \
            cp16(smem_u32(BS + ((ST) * 16 + br) * LDB + bc * 8), W + go);         \
        }                                                                         \
        cp_commit();                                                              \
    }

    ISSUE(0, 0);
    ISSUE(1, 1);

    float acc[4][5][4];
    #pragma unroll
    for (int mi = 0; mi < 4; mi++)
        #pragma unroll
        for (int ni = 0; ni < 5; ni++)
            #pragma unroll
            for (int q = 0; q < 4; q++) acc[mi][ni][q] = 0.f;

    int lr = lane & 15, lkh = (lane >> 4) * 8;

    for (int ch = 0; ch < NCH; ch++) {
        if (ch + 2 < NCH) cp_wait1(); else cp_wait0();
        __syncthreads();
        int st = ch % 3;
        if (ch + 2 < NCH) ISSUE(ch + 2, (ch + 2) % 3);

        uint32_t bh[5][2];
        #pragma unroll
        for (int ni = 0; ni < 5; ni++)
            ldsm_x2t(bh[ni], smem_u32(BS + (st * 16 + lr) * LDB + warp_n * 40 + ni * 8));

        #pragma unroll
        for (int mi = 0; mi < 4; mi++) {
            uint32_t ah[4];
            ldsm_x4(ah, smem_u32(AS + (st * BM + warp_m * 64 + mi * 16 + lr) * LDA + lkh));
            #pragma unroll
            for (int ni = 0; ni < 5; ni++)
                mma16816(acc[mi][ni], ah, bh[ni]);
        }
    }
    #undef ISSUE

    // epilogue: fp16 store + fp32 column stats (bias folded via K-row)
    float se[5], so[5], qe[5], qo[5];
    #pragma unroll
    for (int ni = 0; ni < 5; ni++) { se[ni] = so[ni] = qe[ni] = qo[ni] = 0.f; }

    #pragma unroll
    for (int mi = 0; mi < 4; mi++) {
        int r0 = m0 + warp_m * 64 + mi * 16 + (lane >> 2);
        int r1 = r0 + 8;
        bool v0 = r0 < NN, v1 = r1 < NN;
        #pragma unroll
        for (int ni = 0; ni < 5; ni++) {
            int gn = n0 + warp_n * 40 + ni * 8 + (lane & 3) * 2;
            bool vc = gn < DD;
            float o0 = acc[mi][ni][0], o1 = acc[mi][ni][1];
            float o2 = acc[mi][ni][2], o3 = acc[mi][ni][3];
            if (v0 && vc) *(__half2*)(C + (size_t)r0 * DD + gn) = __floats2half2_rn(o0, o1);
            if (v1 && vc) *(__half2*)(C + (size_t)r1 * DD + gn) = __floats2half2_rn(o2, o3);
            if (v0) { se[ni] += o0; so[ni] += o1; qe[ni] += o0 * o0; qo[ni] += o1 * o1; }
            if (v1) { se[ni] += o2; so[ni] += o3; qe[ni] += o2 * o2; qo[ni] += o3 * o3; }
        }
    }
    #pragma unroll
    for (int ni = 0; ni < 5; ni++) {
        #pragma unroll
        for (int d = 4; d < 32; d <<= 1) {
            se[ni] += __shfl_xor_sync(0xffffffffu, se[ni], d);
            so[ni] += __shfl_xor_sync(0xffffffffu, so[ni], d);
            qe[ni] += __shfl_xor_sync(0xffffffffu, qe[ni], d);
            qo[ni] += __shfl_xor_sync(0xffffffffu, qo[ni], d);
        }
    }
    if (lane < 4) {
        #pragma unroll
        for (int ni = 0; ni < 5; ni++) {
            int gn = n0 + warp_n * 40 + ni * 8 + lane * 2;
            if (gn < DD) {
                atomicAdd(&g_colsum[gn], se[ni]);
                atomicAdd(&g_colsum[gn + 1], so[ni]);
                atomicAdd(&g_colsq[gn], qe[ni]);
                atomicAdd(&g_colsq[gn + 1], qo[ni]);
            }
        }
    }
}

__global__ void k_finalize(int phase, const float* __restrict__ gam,
                           const float* __restrict__ bet) {
    int i = threadIdx.x;
    if (i >= DD) return;
    float m = g_colsum[i] * (1.f / NN);
    float v = g_colsq[i] * (1.f / NN) - m * m;
    float r = rsqrtf(v + BN_EPS);
    float sc = r * gam[i];
    float sh = bet[i] - m * sc;
    if (phase == 0) { g_sc1h[i] = __float2half_rn(sc); g_sh1h[i] = __float2half_rn(sh); }
    else            { g_sc2h[i] = __float2half_rn(sc); g_sh2h[i] = __float2half_rn(sh); }
    g_colsum[i] = 0.f;
    g_colsq[i] = 0.f;
}

// relu(z1h*sc1+sh1) -> g_a (GEMM2 input), uint2-vectorized (4 halves/thread)
__global__ void k_bnsplit() {
    int idx = blockIdx.x * 256 + threadIdx.x;
    if (idx >= NN * 75) return;
    int row = idx / 75, c4 = idx - row * 75;      // cols 4c4..4c4+3
    uint2 z = *(const uint2*)(g_z1h + (size_t)row * DD + 4 * c4);
    uint2 scu = *(const uint2*)(g_sc1h + 4 * c4);
    uint2 shu = *(const uint2*)(g_sh1h + 4 * c4);
    __half2* zp = (__half2*)&z;
    __half2* scp = (__half2*)&scu;
    __half2* shp = (__half2*)&shu;
    __half2 zero = __floats2half2_rn(0.f, 0.f);
    uint2 o;
    ((__half2*)&o)[0] = __hmax2(__hfma2(zp[0], scp[0], shp[0]), zero);
    ((__half2*)&o)[1] = __hmax2(__hfma2(zp[1], scp[1], shp[1]), zero);
    *(uint2*)(g_a + (size_t)row * KP + 4 * c4) = o;
}

// relu(z0h*sc2+sh2) -> g_hbuf, uint2-vectorized
__global__ void k_bnrelu() {
    int idx = blockIdx.x * 256 + threadIdx.x;
    if (idx >= NN * 75) return;
    int row = idx / 75, c4 = idx - row * 75;
    uint2 z = *(const uint2*)(g_z0h + (size_t)row * DD + 4 * c4);
    uint2 scu = *(const uint2*)(g_sc2h + 4 * c4);
    uint2 shu = *(const uint2*)(g_sh2h + 4 * c4);
    __half2* zp = (__half2*)&z;
    __half2* scp = (__half2*)&scu;
    __half2* shp = (__half2*)&shu;
    __half2 zero = __floats2half2_rn(0.f, 0.f);
    uint2 o;
    ((__half2*)&o)[0] = __hmax2(__hfma2(zp[0], scp[0], shp[0]), zero);
    ((__half2*)&o)[1] = __hmax2(__hfma2(zp[1], scp[1], shp[1]), zero);
    *(uint2*)(g_hbuf + (size_t)row * KP + 4 * c4) = o;
}

// pool: read g_hbuf raw (already bnrelu'd or fp16 x)
__global__ void k_pool(int depth) {
    int g = blockIdx.x;
    int c2 = blockIdx.y * 128 + threadIdx.x;
    if (c2 >= 150) return;
    int s0 = g_goff[g], s1 = g_goff[g + 1];
    s0 = max(0, min(NN, s0));
    s1 = max(s0, min(NN, s1));
    float ax = 0.f, ay = 0.f;
    for (int i = s0; i < s1; i++) {
        float2 f = __half22float2(*(const __half2*)(g_hbuf + (size_t)i * KP + 2 * c2));
        ax += f.x; ay += f.y;
    }
    float inv = 1.f / fmaxf((float)(s1 - s0), 1.f);
    float* pr = g_pooled + ((size_t)depth * NGR + g) * DD + 2 * c2;
    pr[0] = ax * inv;
    pr[1] = ay * inv;
}

__global__ void k_readout(const float* __restrict__ fcW, const float* __restrict__ fcb,
                          float* __restrict__ out) {
    __shared__ float sp[DD];
    int g = blockIdx.x, c = threadIdx.x;
    float acc = 0.f;
    for (int d = 0; d <= LL; d++) {
        const float* pr = g_pooled + ((size_t)d * NGR + g) * DD;
        for (int f = c; f < DD; f += 128) sp[f] = pr[f];
        __syncthreads();
        const float* W = fcW + (size_t)d * DD * CC;
        float a = 0.f;
        #pragma unroll 4
        for (int k = 0; k < DD; k++) a += sp[k] * W[k * CC + c];
        acc += a + fcb[d * CC + c];
        __syncthreads();
    }
    out[g * CC + c] = acc;
}

// ---------------- launch ----------------
extern "C" void kernel_launch(void* const* d_in, const int* in_sizes, int n_in,
                              void* d_out, int out_size) {
    const float* x     = (const float*)d_in[0];
    const void*  ei    = d_in[1];
    const void*  batch = d_in[2];
    const float* W1  = (const float*)d_in[3];
    const float* b1  = (const float*)d_in[4];
    const float* g1  = (const float*)d_in[5];
    const float* be1 = (const float*)d_in[6];
    const float* W2  = (const float*)d_in[7];
    const float* b2  = (const float*)d_in[8];
    const float* bng = (const float*)d_in[9];
    const float* bnb = (const float*)d_in[10];
    const float* fcW = (const float*)d_in[11];
    const float* fcb = (const float*)d_in[12];
    float* out = (float*)d_out;

    cudaFuncSetAttribute(k_gemm, cudaFuncAttributeMaxDynamicSharedMemorySize, SMEMSZ);

    k_detect<<<1, 1>>>(ei);
    k_wprep<<<2 * LL * KP, WNP>>>(W1, b1, W2, b2);
    k_xhalf<<<(int)(((long long)NN * KP2 + 255) / 256), 256>>>(x);
    k_padtail<<<8, 256>>>();
    k_zero<<<(NN + 255) / 256, 256>>>();
    k_count<<<(EE + 255) / 256, 256>>>(ei);
    int nb = (NN + 511) / 512;
    k_scan1<<<nb, 512>>>();
    k_scan2<<<1, 128>>>(nb);
    k_scan3<<<(NN + 255) / 256, 256>>>();
    k_fill<<<(EE + 255) / 256, 256>>>(ei);
    k_goff<<<1, 288>>>(batch);

    dim3 pg(NGR, 2);
    k_pool<<<pg, 128>>>(0);

    dim3 gg(2, MT);
    int bn_grid = (NN * 75 + 255) / 256;
    for (int i = 0; i < LL; i++) {
        k_agg<<<(NN + 7) / 8, 256>>>();
        k_gemm<<<gg, 256, SMEMSZ>>>(2 * i, 0);
        k_finalize<<<1, 320>>>(0, g1 + i * DD, be1 + i * DD);
        k_bnsplit<<<bn_grid, 256>>>();
        k_gemm<<<gg, 256, SMEMSZ>>>(2 * i + 1, 1);
        k_finalize<<<1, 320>>>(1, bng + i * DD, bnb + i * DD);
        k_bnrelu<<<bn_grid, 256>>>();
        k_pool<<<pg, 128>>>(i + 1);
    }

    k_readout<<<NGR, 128>>>(fcW, fcb, out);
}

// round 16
// speedup vs baseline: 1.2446x; 1.0197x over previous
#include <cuda_runtime.h>
#include <cuda_fp16.h>
#include <cstdint>

#define NN 50000
#define NNP 50048
#define EE 400000
#define DD 300
#define KP 304
#define KP2 152
#define KU4 38
#define WNP 320
#define LL 5
#define CC 128
#define NGR 256
#define BN_EPS 1e-5f

#define BM 128
#define BN 160
#define NCH 19
#define MT ((NNP) / BM)
#define LDA 24
#define LDB 168
#define STG 3
#define SMEMSZ (STG * (BM * LDA + 16 * LDB) * 2)   // 34560

// ---------------- static device scratch ----------------
__device__ int   g_is64;
__device__ int   g_cnt[NN];
__device__ int   g_off[NN + 1];
__device__ int   g_pos[NN];
__device__ int   g_srcl[EE];
__device__ int   g_goff[NGR + 1];
__device__ int   g_bsum[128];
__device__ int   g_bpre[128];
__device__ __align__(16) __half g_z0h[(size_t)NN * DD];   // GEMM2 out
__device__ __align__(16) __half g_z1h[(size_t)NN * DD];   // GEMM1 out
__device__ __align__(16) __half g_hbuf[(size_t)NN * KP];  // bnrelu'd h / fp16(x), padded
__device__ __align__(16) __half g_a[(size_t)NNP * KP];    // GEMM A operand
__device__ __align__(16) __half g_w[(size_t)2 * LL * KP * WNP];
__device__ float g_colsum[DD];
__device__ float g_colsq[DD];
__device__ __align__(16) __half g_sc1h[DD], g_sh1h[DD], g_sc2h[DD], g_sh2h[DD];
__device__ __align__(16) float g_pooled[(size_t)(LL + 1) * NGR * DD];

// ---------------- PTX helpers ----------------
__device__ __forceinline__ void gdep_wait() {
    asm volatile("griddepcontrol.wait;" ::: "memory");
}
__device__ __forceinline__ uint32_t smem_u32(const void* p) {
    uint32_t a;
    asm("{ .reg .u64 t; cvta.to.shared.u64 t, %1; cvt.u32.u64 %0, t; }" : "=r"(a) : "l"(p));
    return a;
}
__device__ __forceinline__ void cp16(uint32_t d, const void* s) {
    asm volatile("cp.async.cg.shared.global [%0], [%1], 16;" :: "r"(d), "l"(s) : "memory");
}
__device__ __forceinline__ void cp_commit() {
    asm volatile("cp.async.commit_group;" ::: "memory");
}
__device__ __forceinline__ void cp_wait0() {
    asm volatile("cp.async.wait_group 0;" ::: "memory");
}
__device__ __forceinline__ void cp_wait1() {
    asm volatile("cp.async.wait_group 1;" ::: "memory");
}
__device__ __forceinline__ void ldsm_x4(uint32_t* r, uint32_t addr) {
    asm volatile("ldmatrix.sync.aligned.m8n8.x4.shared.b16 {%0,%1,%2,%3}, [%4];"
                 : "=r"(r[0]), "=r"(r[1]), "=r"(r[2]), "=r"(r[3]) : "r"(addr));
}
__device__ __forceinline__ void ldsm_x2t(uint32_t* r, uint32_t addr) {
    asm volatile("ldmatrix.sync.aligned.m8n8.x2.trans.shared.b16 {%0,%1}, [%2];"
                 : "=r"(r[0]), "=r"(r[1]) : "r"(addr));
}
__device__ __forceinline__ void mma16816(float* d, const uint32_t* a, const uint32_t* b) {
    asm volatile("mma.sync.aligned.m16n8k16.row.col.f32.f16.f16.f32 "
                 "{%0,%1,%2,%3}, {%4,%5,%6,%7}, {%8,%9}, {%0,%1,%2,%3};"
                 : "+f"(d[0]), "+f"(d[1]), "+f"(d[2]), "+f"(d[3])
                 : "r"(a[0]), "r"(a[1]), "r"(a[2]), "r"(a[3]), "r"(b[0]), "r"(b[1]));
}
__device__ __forceinline__ int idx_at(const void* p, long long i) {
    if (g_is64) return (int)((const long long*)p)[i];
    return ((const int*)p)[i];
}

// ---------------- setup kernels ----------------
// zero counters + detect index dtype (thread 0 of block 0)
__global__ void k_zero(const void* ei) {
    gdep_wait();
    int i = blockIdx.x * blockDim.x + threadIdx.x;
    if (i == 0) {
        const int* w = (const int*)ei;
        int all0 = 1;
        for (int q = 0; q < 128; q++)
            if (w[2 * q + 1] != 0) { all0 = 0; break; }
        g_is64 = all0;
    }
    if (i < NN) g_cnt[i] = 0;
    if (i < DD) { g_colsum[i] = 0.f; g_colsq[i] = 0.f; }
}

__global__ void k_wprep(const float* __restrict__ W1, const float* __restrict__ b1,
                        const float* __restrict__ W2, const float* __restrict__ b2) {
    gdep_wait();
    int lw = blockIdx.x / KP;
    int k  = blockIdx.x % KP;
    int n  = threadIdx.x;
    int layer = lw >> 1;
    const float* W = (lw & 1) ? W2 : W1;
    const float* b = (lw & 1) ? b2 : b1;
    float v = 0.f;
    if (n < DD) {
        if (k < DD)       v = W[(size_t)layer * DD * DD + (size_t)k * DD + n];
        else if (k == DD) v = b[layer * DD + n];
    }
    g_w[(size_t)lw * KP * WNP + (size_t)k * WNP + n] = __float2half_rn(v);
}

// fp16(x) -> g_hbuf (KP stride, pad cols zeroed) + zero g_a tail rows
__global__ void k_xhalf(const float* __restrict__ x) {
    gdep_wait();
    long long idx = (long long)blockIdx.x * 256 + threadIdx.x;
    const long long NXH = (long long)NN * KP2;
    if (idx < NXH) {
        int row = (int)(idx / KP2), c2 = (int)(idx - (long long)row * KP2);
        __half2 v = __floats2half2_rn(0.f, 0.f);
        if (c2 < 150) {
            float2 f = *(const float2*)(x + (size_t)row * DD + 2 * c2);
            v = __floats2half2_rn(f.x, f.y);
        }
        *(__half2*)(g_hbuf + (size_t)row * KP + 2 * c2) = v;
    } else {
        long long j = idx - NXH;
        if (j < (long long)(NNP - NN) * KU4) {
            int row = NN + (int)(j / KU4), s = (int)(j % KU4);
            ((uint4*)g_a)[(size_t)row * KU4 + s] = make_uint4(0, 0, 0, 0);
        }
    }
}

__global__ void k_count(const void* __restrict__ ei) {
    gdep_wait();
    int e = blockIdx.x * blockDim.x + threadIdx.x;
    if (e < EE) {
        int d = idx_at(ei, (long long)EE + e);
        d = max(0, min(NN - 1, d));
        atomicAdd(&g_cnt[d], 1);
    }
}

__global__ void k_scan1() {
    gdep_wait();
    __shared__ int s[512];
    int b = blockIdx.x, t = threadIdx.x, i = b * 512 + t;
    int v = (i < NN) ? g_cnt[i] : 0;
    s[t] = v;
    __syncthreads();
    for (int d = 1; d < 512; d <<= 1) {
        int y = (t >= d) ? s[t - d] : 0;
        __syncthreads();
        s[t] += y;
        __syncthreads();
    }
    if (i < NN) g_cnt[i] = s[t] - v;
    if (t == 511) g_bsum[b] = s[511];
}
__global__ void k_scan2(int nb) {
    gdep_wait();
    __shared__ int s[128];
    int t = threadIdx.x;
    int v = (t < nb) ? g_bsum[t] : 0;
    s[t] = v;
    __syncthreads();
    for (int d = 1; d < 128; d <<= 1) {
        int y = (t >= d) ? s[t - d] : 0;
        __syncthreads();
        s[t] += y;
        __syncthreads();
    }
    if (t < nb) g_bpre[t] = s[t] - v;
    if (t == nb - 1) g_off[NN] = s[t];
}
// scan3 + goff (graph offsets done by last block's threads)
__global__ void k_scan3(const void* __restrict__ batch) {
    gdep_wait();
    int i = blockIdx.x * blockDim.x + threadIdx.x;
    if (i < NN) {
        int e = g_bpre[i >> 9] + g_cnt[i];
        g_off[i] = e;
        g_pos[i] = e;
    }
    if (blockIdx.x >= gridDim.x - 2) {
        int g = (blockIdx.x - (gridDim.x - 2)) * blockDim.x + threadIdx.x;
        if (g <= NGR) {
            int lo = 0, hi = NN;
            while (lo < hi) {
                int mid = (lo + hi) >> 1;
                if (idx_at(batch, mid) < g) lo = mid + 1; else hi = mid;
            }
            g_goff[g] = lo;
        }
    }
}

__global__ void k_fill(const void* __restrict__ ei) {
    gdep_wait();
    int e = blockIdx.x * blockDim.x + threadIdx.x;
    if (e < EE) {
        int d = idx_at(ei, (long long)EE + e);
        d = max(0, min(NN - 1, d));
        int srcv = idx_at(ei, e);
        srcv = max(0, min(NN - 1, srcv));
        int p = atomicAdd(&g_pos[d], 1);
        if (p >= 0 && p < EE) g_srcl[p] = srcv;
    }
}

// ---------------- aggregation: warp/node, uint4 + HADD2 ----------------
__global__ void __launch_bounds__(256) k_agg() {
    gdep_wait();
    int w = blockIdx.x * 8 + (threadIdx.x >> 5);
    int lane = threadIdx.x & 31;
    if (w >= NN) return;
    const uint4* hb = (const uint4*)g_hbuf;
    const uint4* rowp = hb + (size_t)w * KU4;
    bool hasB = lane < (KU4 - 32);   // lanes 0..5

    uint4 va = rowp[lane];
    uint4 vb = hasB ? rowp[32 + lane] : make_uint4(0, 0, 0, 0);
    __half2 aA[4], aB[4];
    *(uint4*)aA = va;
    *(uint4*)aB = vb;

    int s0 = g_off[w], s1 = g_off[w + 1];
    s0 = max(0, min(EE, s0));
    s1 = max(s0, min(EE, s1));

    for (int j = s0; j < s1; j++) {
        int src = g_srcl[j];
        const uint4* r2 = hb + (size_t)src * KU4;
        uint4 u = r2[lane];
        __half2* up = (__half2*)&u;
        aA[0] = __hadd2(aA[0], up[0]);
        aA[1] = __hadd2(aA[1], up[1]);
        aA[2] = __hadd2(aA[2], up[2]);
        aA[3] = __hadd2(aA[3], up[3]);
        if (hasB) {
            uint4 u2 = r2[32 + lane];
            __half2* vp = (__half2*)&u2;
            aB[0] = __hadd2(aB[0], vp[0]);
            aB[1] = __hadd2(aB[1], vp[1]);
            aB[2] = __hadd2(aB[2], vp[2]);
            aB[3] = __hadd2(aB[3], vp[3]);
        }
    }

    // bias cols 300..303 = {1,0,0,0} (lane 5 slot B = cols 296..303)
    if (lane == 5) {
        aB[2] = __floats2half2_rn(1.f, 0.f);
        aB[3] = __floats2half2_rn(0.f, 0.f);
    }

    uint4* ar = (uint4*)g_a + (size_t)w * KU4;
    ar[lane] = *(uint4*)aA;
    if (hasB) ar[32 + lane] = *(uint4*)aB;
}

// ---------------- fp16 GEMM: C(half) = A @ W, fp32 stats ----------------
__global__ void __launch_bounds__(256, 2) k_gemm(int widx, int phase) {
    gdep_wait();
    extern __shared__ __align__(16) char smem[];
    __half* AS = (__half*)smem;                   // [STG][BM][LDA]
    __half* BS = AS + STG * BM * LDA;             // [STG][16][LDB]

    __half* __restrict__ C = phase ? g_z0h : g_z1h;
    const __half* __restrict__ W = g_w + (size_t)widx * KP * WNP;

    int tid = threadIdx.x, lane = tid & 31, wid = tid >> 5;
    int warp_m = wid & 1, warp_n = wid >> 1;
    int m0 = blockIdx.y * BM, n0 = blockIdx.x * BN;

    int arow = tid >> 1, aseg = tid & 1;
    const __half* asrc = g_a + (size_t)(m0 + arow) * KP + aseg * 8;

    #define ISSUE(CH, ST)                                                         \
    {                                                                             \
        int k0i = (CH) * 16;                                                      \
        cp16(smem_u32(AS + ((ST) * BM + arow) * LDA + aseg * 8), asrc + k0i);     \
        for (int u = tid; u < 320; u += 256) {                                    \
            int br = u / 20, bc = u % 20;                                         \
            size_t go = (size_t)(k0i + br) * WNP + n0 + bc * 8;                   \
            cp16(smem_u32(BS + ((ST) * 16 + br) * LDB + bc * 8), W + go);         \
        }                                                                         \
        cp_commit();                                                              \
    }

    ISSUE(0, 0);
    ISSUE(1, 1);

    float acc[4][5][4];
    #pragma unroll
    for (int mi = 0; mi < 4; mi++)
        #pragma unroll
        for (int ni = 0; ni < 5; ni++)
            #pragma unroll
            for (int q = 0; q < 4; q++) acc[mi][ni][q] = 0.f;

    int lr = lane & 15, lkh = (lane >> 4) * 8;

    for (int ch = 0; ch < NCH; ch++) {
        if (ch + 2 < NCH) cp_wait1(); else cp_wait0();
        __syncthreads();
        int st = ch % 3;
        if (ch + 2 < NCH) ISSUE(ch + 2, (ch + 2) % 3);

        uint32_t bh[5][2];
        #pragma unroll
        for (int ni = 0; ni < 5; ni++)
            ldsm_x2t(bh[ni], smem_u32(BS + (st * 16 + lr) * LDB + warp_n * 40 + ni * 8));

        #pragma unroll
        for (int mi = 0; mi < 4; mi++) {
            uint32_t ah[4];
            ldsm_x4(ah, smem_u32(AS + (st * BM + warp_m * 64 + mi * 16 + lr) * LDA + lkh));
            #pragma unroll
            for (int ni = 0; ni < 5; ni++)
                mma16816(acc[mi][ni], ah, bh[ni]);
        }
    }
    #undef ISSUE

    // epilogue: fp16 store + fp32 column stats (bias folded via K-row)
    float se[5], so[5], qe[5], qo[5];
    #pragma unroll
    for (int ni = 0; ni < 5; ni++) { se[ni] = so[ni] = qe[ni] = qo[ni] = 0.f; }

    #pragma unroll
    for (int mi = 0; mi < 4; mi++) {
        int r0 = m0 + warp_m * 64 + mi * 16 + (lane >> 2);
        int r1 = r0 + 8;
        bool v0 = r0 < NN, v1 = r1 < NN;
        #pragma unroll
        for (int ni = 0; ni < 5; ni++) {
            int gn = n0 + warp_n * 40 + ni * 8 + (lane & 3) * 2;
            bool vc = gn < DD;
            float o0 = acc[mi][ni][0], o1 = acc[mi][ni][1];
            float o2 = acc[mi][ni][2], o3 = acc[mi][ni][3];
            if (v0 && vc) *(__half2*)(C + (size_t)r0 * DD + gn) = __floats2half2_rn(o0, o1);
            if (v1 && vc) *(__half2*)(C + (size_t)r1 * DD + gn) = __floats2half2_rn(o2, o3);
            if (v0) { se[ni] += o0; so[ni] += o1; qe[ni] += o0 * o0; qo[ni] += o1 * o1; }
            if (v1) { se[ni] += o2; so[ni] += o3; qe[ni] += o2 * o2; qo[ni] += o3 * o3; }
        }
    }
    #pragma unroll
    for (int ni = 0; ni < 5; ni++) {
        #pragma unroll
        for (int d = 4; d < 32; d <<= 1) {
            se[ni] += __shfl_xor_sync(0xffffffffu, se[ni], d);
            so[ni] += __shfl_xor_sync(0xffffffffu, so[ni], d);
            qe[ni] += __shfl_xor_sync(0xffffffffu, qe[ni], d);
            qo[ni] += __shfl_xor_sync(0xffffffffu, qo[ni], d);
        }
    }
    if (lane < 4) {
        #pragma unroll
        for (int ni = 0; ni < 5; ni++) {
            int gn = n0 + warp_n * 40 + ni * 8 + lane * 2;
            if (gn < DD) {
                atomicAdd(&g_colsum[gn], se[ni]);
                atomicAdd(&g_colsum[gn + 1], so[ni]);
                atomicAdd(&g_colsq[gn], qe[ni]);
                atomicAdd(&g_colsq[gn + 1], qo[ni]);
            }
        }
    }
}

__global__ void k_finalize(int phase, const float* __restrict__ gam,
                           const float* __restrict__ bet) {
    gdep_wait();
    int i = threadIdx.x;
    if (i >= DD) return;
    float m = g_colsum[i] * (1.f / NN);
    float v = g_colsq[i] * (1.f / NN) - m * m;
    float r = rsqrtf(v + BN_EPS);
    float sc = r * gam[i];
    float sh = bet[i] - m * sc;
    if (phase == 0) { g_sc1h[i] = __float2half_rn(sc); g_sh1h[i] = __float2half_rn(sh); }
    else            { g_sc2h[i] = __float2half_rn(sc); g_sh2h[i] = __float2half_rn(sh); }
    g_colsum[i] = 0.f;
    g_colsq[i] = 0.f;
}

// relu(z1h*sc1+sh1) -> g_a (GEMM2 input), uint2-vectorized (4 halves/thread)
__global__ void k_bnsplit() {
    gdep_wait();
    int idx = blockIdx.x * 256 + threadIdx.x;
    if (idx >= NN * 75) return;
    int row = idx / 75, c4 = idx - row * 75;      // cols 4c4..4c4+3
    uint2 z = *(const uint2*)(g_z1h + (size_t)row * DD + 4 * c4);
    uint2 scu = *(const uint2*)(g_sc1h + 4 * c4);
    uint2 shu = *(const uint2*)(g_sh1h + 4 * c4);
    __half2* zp = (__half2*)&z;
    __half2* scp = (__half2*)&scu;
    __half2* shp = (__half2*)&shu;
    __half2 zero = __floats2half2_rn(0.f, 0.f);
    uint2 o;
    ((__half2*)&o)[0] = __hmax2(__hfma2(zp[0], scp[0], shp[0]), zero);
    ((__half2*)&o)[1] = __hmax2(__hfma2(zp[1], scp[1], shp[1]), zero);
    *(uint2*)(g_a + (size_t)row * KP + 4 * c4) = o;
}

// relu(z0h*sc2+sh2) -> g_hbuf, uint2-vectorized
__global__ void k_bnrelu() {
    gdep_wait();
    int idx = blockIdx.x * 256 + threadIdx.x;
    if (idx >= NN * 75) return;
    int row = idx / 75, c4 = idx - row * 75;
    uint2 z = *(const uint2*)(g_z0h + (size_t)row * DD + 4 * c4);
    uint2 scu = *(const uint2*)(g_sc2h + 4 * c4);
    uint2 shu = *(const uint2*)(g_sh2h + 4 * c4);
    __half2* zp = (__half2*)&z;
    __half2* scp = (__half2*)&scu;
    __half2* shp = (__half2*)&shu;
    __half2 zero = __floats2half2_rn(0.f, 0.f);
    uint2 o;
    ((__half2*)&o)[0] = __hmax2(__hfma2(zp[0], scp[0], shp[0]), zero);
    ((__half2*)&o)[1] = __hmax2(__hfma2(zp[1], scp[1], shp[1]), zero);
    *(uint2*)(g_hbuf + (size_t)row * KP + 4 * c4) = o;
}

// pool: read g_hbuf raw (already bnrelu'd or fp16 x)
__global__ void k_pool(int depth) {
    gdep_wait();
    int g = blockIdx.x;
    int c2 = blockIdx.y * 128 + threadIdx.x;
    if (c2 >= 150) return;
    int s0 = g_goff[g], s1 = g_goff[g + 1];
    s0 = max(0, min(NN, s0));
    s1 = max(s0, min(NN, s1));
    float ax = 0.f, ay = 0.f;
    for (int i = s0; i < s1; i++) {
        float2 f = __half22float2(*(const __half2*)(g_hbuf + (size_t)i * KP + 2 * c2));
        ax += f.x; ay += f.y;
    }
    float inv = 1.f / fmaxf((float)(s1 - s0), 1.f);
    float* pr = g_pooled + ((size_t)depth * NGR + g) * DD + 2 * c2;
    pr[0] = ax * inv;
    pr[1] = ay * inv;
}

__global__ void k_readout(const float* __restrict__ fcW, const float* __restrict__ fcb,
                          float* __restrict__ out) {
    gdep_wait();
    __shared__ float sp[DD];
    int g = blockIdx.x, c = threadIdx.x;
    float acc = 0.f;
    for (int d = 0; d <= LL; d++) {
        const float* pr = g_pooled + ((size_t)d * NGR + g) * DD;
        for (int f = c; f < DD; f += 128) sp[f] = pr[f];
        __syncthreads();
        const float* W = fcW + (size_t)d * DD * CC;
        float a = 0.f;
        #pragma unroll 4
        for (int k = 0; k < DD; k++) a += sp[k] * W[k * CC + c];
        acc += a + fcb[d * CC + c];
        __syncthreads();
    }
    out[g * CC + c] = acc;
}

// ---------------- PDL launch helper ----------------
template <class... A, class... B>
static void launch_pdl(void (*kern)(A...), dim3 g, dim3 b, size_t smem, B... args) {
    cudaLaunchConfig_t cfg = {};
    cfg.gridDim = g;
    cfg.blockDim = b;
    cfg.dynamicSmemBytes = smem;
    cfg.stream = 0;
    cudaLaunchAttribute at[1];
    at[0].id = cudaLaunchAttributeProgrammaticStreamSerialization;
    at[0].val.programmaticStreamSerializationAllowed = 1;
    cfg.attrs = at;
    cfg.numAttrs = 1;
    cudaLaunchKernelEx(&cfg, kern, (A)args...);
}

// ---------------- launch ----------------
extern "C" void kernel_launch(void* const* d_in, const int* in_sizes, int n_in,
                              void* d_out, int out_size) {
    const float* x     = (const float*)d_in[0];
    const void*  ei    = d_in[1];
    const void*  batch = d_in[2];
    const float* W1  = (const float*)d_in[3];
    const float* b1  = (const float*)d_in[4];
    const float* g1  = (const float*)d_in[5];
    const float* be1 = (const float*)d_in[6];
    const float* W2  = (const float*)d_in[7];
    const float* b2  = (const float*)d_in[8];
    const float* bng = (const float*)d_in[9];
    const float* bnb = (const float*)d_in[10];
    const float* fcW = (const float*)d_in[11];
    const float* fcb = (const float*)d_in[12];
    float* out = (float*)d_out;

    cudaFuncSetAttribute(k_gemm, cudaFuncAttributeMaxDynamicSharedMemorySize, SMEMSZ);

    launch_pdl(k_zero, dim3((NN + 255) / 256), dim3(256), 0, ei);
    launch_pdl(k_wprep, dim3(2 * LL * KP), dim3(WNP), 0, W1, b1, W2, b2);
    long long nxh = (long long)NN * KP2 + (long long)(NNP - NN) * KU4;
    launch_pdl(k_xhalf, dim3((int)((nxh + 255) / 256)), dim3(256), 0, x);
    launch_pdl(k_count, dim3((EE + 255) / 256), dim3(256), 0, ei);
    int nb = (NN + 511) / 512;
    launch_pdl(k_scan1, dim3(nb), dim3(512), 0);
    launch_pdl(k_scan2, dim3(1), dim3(128), 0, nb);
    launch_pdl(k_scan3, dim3((NN + 255) / 256), dim3(256), 0, batch);
    launch_pdl(k_fill, dim3((EE + 255) / 256), dim3(256), 0, ei);

    dim3 pg(NGR, 2);
    launch_pdl(k_pool, pg, dim3(128), 0, 0);

    dim3 gg(2, MT);
    int bn_grid = (NN * 75 + 255) / 256;
    for (int i = 0; i < LL; i++) {
        launch_pdl(k_agg, dim3((NN + 7) / 8), dim3(256), 0);
        launch_pdl(k_gemm, gg, dim3(256), SMEMSZ, 2 * i, 0);
        launch_pdl(k_finalize, dim3(1), dim3(320), 0, 0, g1 + i * DD, be1 + i * DD);
        launch_pdl(k_bnsplit, dim3(bn_grid), dim3(256), 0);
        launch_pdl(k_gemm, gg, dim3(256), SMEMSZ, 2 * i + 1, 1);
        launch_pdl(k_finalize, dim3(1), dim3(320), 0, 1, bng + i * DD, bnb + i * DD);
        launch_pdl(k_bnrelu, dim3(bn_grid), dim3(256), 0);
        launch_pdl(k_pool, pg, dim3(128), 0, i + 1);
    }

    launch_pdl(k_readout, dim3(NGR), dim3(128), 0, fcW, fcb, out);
}